// round 15
// baseline (speedup 1.0000x reference)
#include <cuda_runtime.h>
#include <cuda_bf16.h>
#include <math.h>
#include <stdint.h>

#define LLS 2048
#define DDM 512
#define NZ  16                 // B*H
#define TOKENS 4096
#define OUT_ELEMS (TOKENS*DDM)
#define SA 72                  // padded K-stride for 64-wide operand tiles
#define NEGINF __int_as_float(0xff800000)

// ------------------------- scratch (no allocs) -----------------------------
__device__ __align__(16) __nv_bfloat16 g_in_hi[3*TOKENS*DDM];   // q,k,v pre-split
__device__ __align__(16) __nv_bfloat16 g_in_lo[3*TOKENS*DDM];
__device__ __align__(16) __nv_bfloat16 g_w_hi[4*DDM*DDM];       // Wq,Wk,Wv,Wo
__device__ __align__(16) __nv_bfloat16 g_w_lo[4*DDM*DDM];
__device__ __align__(16) __nv_bfloat16 g_q_hi[NZ*LLS*64];
__device__ __align__(16) __nv_bfloat16 g_q_lo[NZ*LLS*64];
__device__ __align__(16) __nv_bfloat16 g_k_hi[NZ*LLS*64];
__device__ __align__(16) __nv_bfloat16 g_k_lo[NZ*LLS*64];
__device__ __align__(16) __nv_bfloat16 g_vt_hi[NZ*64*LLS];      // [bz][d][lk]
__device__ __align__(16) __nv_bfloat16 g_vt_lo[NZ*64*LLS];
__device__ __align__(16) __nv_bfloat16 g_ctx_hi[TOKENS*DDM];
__device__ __align__(16) __nv_bfloat16 g_ctx_lo[TOKENS*DDM];
__device__ float g_M[NZ];
__device__ float g_rowI[NZ*LLS];
__device__ float g_tmp[TOKENS*DDM];

// ------------------------------ helpers ------------------------------------
static __device__ __forceinline__ uint32_t cvs(const void* p) {
    uint32_t a;
    asm("{ .reg .u64 t; cvta.to.shared.u64 t, %1; cvt.u32.u64 %0, t; }" : "=r"(a) : "l"(p));
    return a;
}
static __device__ __forceinline__ void ldsm4(uint32_t* r, uint32_t a) {
    asm volatile("ldmatrix.sync.aligned.m8n8.x4.shared.b16 {%0,%1,%2,%3}, [%4];"
        : "=r"(r[0]), "=r"(r[1]), "=r"(r[2]), "=r"(r[3]) : "r"(a));
}
static __device__ __forceinline__ void mma_bf(float* d, const uint32_t* a, uint32_t b0, uint32_t b1) {
    asm volatile("mma.sync.aligned.m16n8k16.row.col.f32.bf16.bf16.f32 "
        "{%0,%1,%2,%3},{%4,%5,%6,%7},{%8,%9},{%0,%1,%2,%3};"
        : "+f"(d[0]), "+f"(d[1]), "+f"(d[2]), "+f"(d[3])
        : "r"(a[0]), "r"(a[1]), "r"(a[2]), "r"(a[3]), "r"(b0), "r"(b1));
}
#define CPC()  asm volatile("cp.async.commit_group;" ::: "memory")
#define CPW0() asm volatile("cp.async.wait_group 0;" ::: "memory")
#define CPW1() asm volatile("cp.async.wait_group 1;" ::: "memory")

static __device__ __forceinline__ void cpa16(uint32_t dst, const void* src) {
    asm volatile("cp.async.cg.shared.global [%0], [%1], 16;" :: "r"(dst), "l"(src));
}
// bf16 [128][64] tile (row stride ld) -> smem [128][SA] via cp.async
static __device__ __forceinline__ void cpa_bf64(const __nv_bfloat16* __restrict__ src, int ld,
                                                uint32_t dst, int tid) {
    #pragma unroll
    for (int i = 0; i < 4; i++) {
        int idx = i * 256 + tid, row = idx >> 3, c = (idx & 7) * 8;
        cpa16(dst + (uint32_t)(row * SA + c) * 2, src + (size_t)row * ld + c);
    }
}
// bf16 [64][64] tile (row stride LLS) -> smem [64][SA] via cp.async
static __device__ __forceinline__ void cpa_v64(const __nv_bfloat16* __restrict__ src,
                                               uint32_t dst, int tid) {
    #pragma unroll
    for (int i = 0; i < 2; i++) {
        int idx = i * 256 + tid, row = idx >> 3, c = (idx & 7) * 8;
        cpa16(dst + (uint32_t)(row * SA + c) * 2, src + (size_t)row * LLS + c);
    }
}
static __device__ __forceinline__ uint32_t pk2(__nv_bfloat16 a, __nv_bfloat16 b) {
    __nv_bfloat162 t = __halves2bfloat162(a, b);
    return *reinterpret_cast<uint32_t*>(&t);
}
static __device__ __forceinline__ void split2(float x, float y, uint32_t& h, uint32_t& l) {
    __nv_bfloat16 hx = __float2bfloat16(x), hy = __float2bfloat16(y);
    h = pk2(hx, hy);
    l = pk2(__float2bfloat16(x - __bfloat162float(hx)),
            __float2bfloat16(y - __bfloat162float(hy)));
}
static __device__ __forceinline__ uint32_t aoff(int row0, int k0, int stride, int lane) {
    return (uint32_t)((row0 + (lane & 15)) * stride + k0 + ((lane >> 4) << 3)) * 2;
}
static __device__ __forceinline__ uint32_t boff(int n0, int k0, int stride, int lane) {
    return (uint32_t)((n0 + ((lane >> 4) << 3) + (lane & 7)) * stride + k0 + (((lane >> 3) & 1) << 3)) * 2;
}

// 3-term split GEMM chunk with B-fragment reuse: c[16][4] += A*B, K=64
static __device__ __forceinline__ void mma_chunk128(float (*c)[4],
        uint32_t sAh, uint32_t sAl, uint32_t sBh, uint32_t sBl, int wrow, int lane) {
    #pragma unroll
    for (int kk = 0; kk < 4; kk++) {
        uint32_t ah[4], al[4];
        ldsm4(ah, sAh + aoff(wrow, kk * 16, SA, lane));
        ldsm4(al, sAl + aoff(wrow, kk * 16, SA, lane));
        #pragma unroll
        for (int g = 0; g < 8; g++) {
            uint32_t bh[4], bl[4];
            ldsm4(bh, sBh + boff(g * 16, kk * 16, SA, lane));
            ldsm4(bl, sBl + boff(g * 16, kk * 16, SA, lane));
            mma_bf(c[2 * g],     ah, bh[0], bh[1]);
            mma_bf(c[2 * g + 1], ah, bh[2], bh[3]);
            mma_bf(c[2 * g],     ah, bl[0], bl[1]);
            mma_bf(c[2 * g + 1], ah, bl[2], bl[3]);
            mma_bf(c[2 * g],     al, bh[0], bh[1]);
            mma_bf(c[2 * g + 1], al, bh[2], bh[3]);
        }
    }
}

// ===========================================================================
// Kernel 0: pre-split fp32 inputs to bf16 hi/lo.
// ===========================================================================
__global__ __launch_bounds__(256) void split_kernel(
    const float* __restrict__ q, const float* __restrict__ k, const float* __restrict__ v,
    const float* __restrict__ Wq, const float* __restrict__ Wk,
    const float* __restrict__ Wv, const float* __restrict__ Wo)
{
    const int z = blockIdx.y;
    const float* src;
    __nv_bfloat16 *hi, *lo;
    int n4;
    if (z < 3) {
        src = (z == 0) ? q : (z == 1) ? k : v;
        hi = g_in_hi + (size_t)z * TOKENS * DDM;
        lo = g_in_lo + (size_t)z * TOKENS * DDM;
        n4 = TOKENS * DDM / 4;
    } else {
        src = (z == 3) ? Wq : (z == 4) ? Wk : (z == 5) ? Wv : Wo;
        hi = g_w_hi + (size_t)(z - 3) * DDM * DDM;
        lo = g_w_lo + (size_t)(z - 3) * DDM * DDM;
        n4 = DDM * DDM / 4;
    }
    for (int i = blockIdx.x * 256 + threadIdx.x; i < n4; i += gridDim.x * 256) {
        float4 f = ((const float4*)src)[i];
        uint32_t h0, l0, h1, l1;
        split2(f.x, f.y, h0, l0);
        split2(f.z, f.w, h1, l1);
        ((uint2*)hi)[i] = make_uint2(h0, h1);
        ((uint2*)lo)[i] = make_uint2(l0, l1);
    }
}

// ===========================================================================
// Kernel 1: projections (pure-bf16, cp.async double-buffered, BK=64).
// ===========================================================================
__global__ __launch_bounds__(256) void proj_kernel(
    const float* __restrict__ bq, const float* __restrict__ bk, const float* __restrict__ bv)
{
    extern __shared__ char sm[];
    const int tid = threadIdx.x, lane = tid & 31, w = tid >> 5;
    const int gid = lane >> 2, tq = lane & 3;
    const int z = blockIdx.z;

    const __nv_bfloat16 *Ah, *Al, *Bh, *Bl;
    const float* bias;
    int m0, n0;
    if (z == 2) {
        m0 = blockIdx.x * 128;   // dim
        n0 = blockIdx.y * 128;   // token
        Ah = g_w_hi + (size_t)2 * DDM * DDM + (size_t)m0 * DDM;
        Al = g_w_lo + (size_t)2 * DDM * DDM + (size_t)m0 * DDM;
        Bh = g_in_hi + (size_t)2 * TOKENS * DDM + (size_t)n0 * DDM;
        Bl = g_in_lo + (size_t)2 * TOKENS * DDM + (size_t)n0 * DDM;
        bias = bv;
    } else {
        m0 = blockIdx.y * 128;   // token
        n0 = blockIdx.x * 128;   // out-dim
        Ah = g_in_hi + (size_t)z * TOKENS * DDM + (size_t)m0 * DDM;
        Al = g_in_lo + (size_t)z * TOKENS * DDM + (size_t)m0 * DDM;
        Bh = g_w_hi + (size_t)z * DDM * DDM + (size_t)n0 * DDM;
        Bl = g_w_lo + (size_t)z * DDM * DDM + (size_t)n0 * DDM;
        bias = (z == 0) ? bq : bk;
    }

    uint32_t s0 = cvs(sm);

    cpa_bf64(Ah, DDM, s0, tid);
    cpa_bf64(Al, DDM, s0 + 18432, tid);
    cpa_bf64(Bh, DDM, s0 + 36864, tid);
    cpa_bf64(Bl, DDM, s0 + 55296, tid);
    CPC();

    float c[16][4];
    #pragma unroll
    for (int i = 0; i < 16; i++)
        #pragma unroll
        for (int j = 0; j < 4; j++) c[i][j] = 0.f;

    for (int c8 = 0; c8 < 8; c8++) {
        CPW0();
        __syncthreads();
        uint32_t sb = s0 + (c8 & 1) * 73728;
        if (c8 < 7) {
            uint32_t sn = s0 + ((c8 + 1) & 1) * 73728;
            int off = (c8 + 1) * 64;
            cpa_bf64(Ah + off, DDM, sn, tid);
            cpa_bf64(Al + off, DDM, sn + 18432, tid);
            cpa_bf64(Bh + off, DDM, sn + 36864, tid);
            cpa_bf64(Bl + off, DDM, sn + 55296, tid);
            CPC();
        }
        mma_chunk128(c, sb, sb + 18432, sb + 36864, sb + 55296, w * 16, lane);
    }

    if (z < 2) {
        __nv_bfloat16* Ohi = (z == 0) ? g_q_hi : g_k_hi;
        __nv_bfloat16* Olo = (z == 0) ? g_q_lo : g_k_lo;
        #pragma unroll
        for (int g = 0; g < 16; g++) {
            int n = n0 + g * 8 + 2 * tq;
            float b0 = bias[n], b1 = bias[n + 1];
            int head = n >> 6, d = n & 63;
            #pragma unroll
            for (int rr = 0; rr < 2; rr++) {
                int t = m0 + w * 16 + gid + rr * 8;
                int bb = t >> 11, l = t & 2047;
                float v0 = c[g][rr * 2] + b0, v1 = c[g][rr * 2 + 1] + b1;
                uint32_t h, lo;
                split2(v0, v1, h, lo);
                size_t base = (((size_t)(bb * 8 + head)) * LLS + l) * 64 + d;
                *(uint32_t*)(Ohi + base) = h;
                *(uint32_t*)(Olo + base) = lo;
            }
        }
    } else {
        #pragma unroll
        for (int g = 0; g < 16; g++) {
            int n = n0 + g * 8 + 2 * tq;     // token
            int bb = n >> 11, l = n & 2047;
            #pragma unroll
            for (int rr = 0; rr < 2; rr++) {
                int m = m0 + w * 16 + gid + rr * 8;   // dim
                int head = m >> 6, d = m & 63;
                float bm = bias[m];
                float v0 = c[g][rr * 2] + bm, v1 = c[g][rr * 2 + 1] + bm;
                uint32_t h, lo;
                split2(v0, v1, h, lo);
                size_t base = (((size_t)(bb * 8 + head)) * 64 + d) * LLS + l;
                *(uint32_t*)(g_vt_hi + base) = h;
                *(uint32_t*)(g_vt_lo + base) = lo;
            }
        }
    }
}

// ===========================================================================
// Kernel 2: per-(b,h) softmax shift M = 0.5*sqrt(mean||q||^2)*sqrt(mean||k||^2)
// ===========================================================================
static __device__ __forceinline__ float ssqw(uint32_t w) {
    float2 f = __bfloat1622float2(*reinterpret_cast<__nv_bfloat162*>(&w));
    return f.x * f.x + f.y * f.y;
}
__global__ __launch_bounds__(256) void normM_kernel()
{
    const int bz = blockIdx.x, tid = threadIdx.x;
    const uint4* qp = (const uint4*)(g_q_hi + (size_t)bz * LLS * 64);
    const uint4* kp = (const uint4*)(g_k_hi + (size_t)bz * LLS * 64);
    float sq = 0.f, sk = 0.f;
    for (int i = tid; i < LLS * 64 / 8; i += 256) {
        uint4 a = qp[i];
        sq += ssqw(a.x) + ssqw(a.y) + ssqw(a.z) + ssqw(a.w);
        uint4 b = kp[i];
        sk += ssqw(b.x) + ssqw(b.y) + ssqw(b.z) + ssqw(b.w);
    }
    __shared__ float r1[8], r2[8];
    #pragma unroll
    for (int o = 16; o; o >>= 1) {
        sq += __shfl_xor_sync(0xffffffffu, sq, o);
        sk += __shfl_xor_sync(0xffffffffu, sk, o);
    }
    if ((tid & 31) == 0) { r1[tid >> 5] = sq; r2[tid >> 5] = sk; }
    __syncthreads();
    if (tid == 0) {
        float a = 0.f, b = 0.f;
        #pragma unroll
        for (int j = 0; j < 8; j++) { a += r1[j]; b += r2[j]; }
        g_M[bz] = 0.5f * sqrtf(a / LLS) * sqrtf(b / LLS);
    }
}

// ===========================================================================
// Kernel 3: single-sweep attention (R7/R10 version, unchanged).
// ===========================================================================
__global__ __launch_bounds__(256, 2) void attn_kernel(
    const unsigned char* __restrict__ mask, float* __restrict__ attn)
{
    extern __shared__ char sm[];
    const int tid = threadIdx.x, lane = tid & 31, w = tid >> 5;
    const int gid = lane >> 2, tq = lane & 3;
    const int m0 = blockIdx.x * 128, zz = blockIdx.y;
    const int h = zz >> 1, b = zz & 1, bz = b * 8 + h;

    uint32_t s0 = cvs(sm);
    const uint32_t sKh = s0, sKl = s0 + 18432;
    const uint32_t sVaH = s0 + 36864, sVaL = s0 + 46080;
    const uint32_t sVbH = s0 + 55296, sVbL = s0 + 64512;

    const __nv_bfloat16* Kh = g_k_hi + (size_t)bz * LLS * 64;
    const __nv_bfloat16* Kl = g_k_lo + (size_t)bz * LLS * 64;
    const __nv_bfloat16* Vh = g_vt_hi + (size_t)bz * 64 * LLS;
    const __nv_bfloat16* Vl = g_vt_lo + (size_t)bz * 64 * LLS;
    const float M = g_M[bz];

    cpa_bf64(g_q_hi + ((size_t)bz * LLS + m0) * 64, 64, sVaH, tid);
    cpa_bf64(g_q_lo + ((size_t)bz * LLS + m0) * 64, 64, sVbH, tid);
    cpa_bf64(Kh, 64, sKh, tid);
    cpa_bf64(Kl, 64, sKl, tid);
    CPC();
    CPW0();
    __syncthreads();

    uint32_t qh[4][4], ql[4][4];
    #pragma unroll
    for (int kk = 0; kk < 4; kk++) {
        ldsm4(qh[kk], sVaH + aoff(w * 16, kk * 16, SA, lane));
        ldsm4(ql[kk], sVbH + aoff(w * 16, kk * 16, SA, lane));
    }
    __syncthreads();

    cpa_v64(Vh, sVaH, tid);      cpa_v64(Vl, sVaL, tid);      CPC();
    cpa_v64(Vh + 64, sVbH, tid); cpa_v64(Vl + 64, sVbL, tid); CPC();

    const int lq0 = m0 + w * 16 + gid;
    float rs0 = 0.f, rs1 = 0.f;

    float cc[8][4];
    #pragma unroll
    for (int i = 0; i < 8; i++)
        #pragma unroll
        for (int j = 0; j < 4; j++) cc[i][j] = 0.f;

    for (int nt = 0; nt < 16; nt++) {
        CPW1();
        __syncthreads();

        const unsigned char* mrow = mask + ((size_t)b * LLS + lq0) * LLS + nt * 128;
        float* prow = attn + ((size_t)zz * LLS + lq0) * LLS + nt * 128;

        #pragma unroll
        for (int half = 0; half < 2; half++) {
            float c[8][4];
            #pragma unroll
            for (int i = 0; i < 8; i++)
                #pragma unroll
                for (int j = 0; j < 4; j++) c[i][j] = 0.f;
            #pragma unroll
            for (int kk = 0; kk < 4; kk++) {
                #pragma unroll
                for (int g = 0; g < 4; g++) {
                    uint32_t bh[4], bl[4];
                    uint32_t off = boff((half * 4 + g) * 16, kk * 16, SA, lane);
                    ldsm4(bh, sKh + off);
                    ldsm4(bl, sKl + off);
                    mma_bf(c[2 * g],     qh[kk], bh[0], bh[1]);
                    mma_bf(c[2 * g + 1], qh[kk], bh[2], bh[3]);
                    mma_bf(c[2 * g],     qh[kk], bl[0], bl[1]);
                    mma_bf(c[2 * g + 1], qh[kk], bl[2], bl[3]);
                    mma_bf(c[2 * g],     ql[kk], bh[0], bh[1]);
                    mma_bf(c[2 * g + 1], ql[kk], bh[2], bh[3]);
                }
            }

            if (half == 1) {
                __syncthreads();
                if (nt < 15) {
                    cpa_bf64(Kh + (size_t)(nt + 1) * 128 * 64, 64, sKh, tid);
                    cpa_bf64(Kl + (size_t)(nt + 1) * 128 * 64, 64, sKl, tid);
                    cpa_v64(Vh + (nt + 1) * 128, sVaH, tid);
                    cpa_v64(Vl + (nt + 1) * 128, sVaL, tid);
                    CPC();
                    CPW1();
                } else {
                    CPW0();
                }
                __syncthreads();
            }

            const unsigned char* mr0 = mrow + half * 64;
            const unsigned char* mr1 = mr0 + (size_t)8 * LLS;
            float* pr0 = prow + half * 64;
            float* pr1 = pr0 + (size_t)8 * LLS;
            #pragma unroll
            for (int g = 0; g < 8; g++) {
                int nn = g * 8 + 2 * tq;
                unsigned short mw0 = *(const unsigned short*)(mr0 + nn);
                unsigned short mw1 = *(const unsigned short*)(mr1 + nn);
                c[g][0] = (mw0 & 0xFF) ? 0.f : __expf(c[g][0] - M);
                c[g][1] = (mw0 >> 8)   ? 0.f : __expf(c[g][1] - M);
                c[g][2] = (mw1 & 0xFF) ? 0.f : __expf(c[g][2] - M);
                c[g][3] = (mw1 >> 8)   ? 0.f : __expf(c[g][3] - M);
                rs0 += c[g][0] + c[g][1];
                rs1 += c[g][2] + c[g][3];
                *(float2*)(pr0 + nn) = make_float2(c[g][0], c[g][1]);
                *(float2*)(pr1 + nn) = make_float2(c[g][2], c[g][3]);
            }

            uint32_t svh = half ? sVbH : sVaH;
            uint32_t svl = half ? sVbL : sVaL;
            #pragma unroll
            for (int kk2 = 0; kk2 < 4; kk2++) {
                uint32_t eh[4], el[4];
                split2(c[2 * kk2][0],     c[2 * kk2][1],     eh[0], el[0]);
                split2(c[2 * kk2][2],     c[2 * kk2][3],     eh[1], el[1]);
                split2(c[2 * kk2 + 1][0], c[2 * kk2 + 1][1], eh[2], el[2]);
                split2(c[2 * kk2 + 1][2], c[2 * kk2 + 1][3], eh[3], el[3]);
                #pragma unroll
                for (int g2 = 0; g2 < 4; g2++) {
                    uint32_t off = boff(g2 * 16, kk2 * 16, SA, lane);
                    uint32_t bh[4], bl[4];
                    ldsm4(bh, svh + off);
                    ldsm4(bl, svl + off);
                    mma_bf(cc[2 * g2],     eh, bh[0], bh[1]);
                    mma_bf(cc[2 * g2 + 1], eh, bh[2], bh[3]);
                    mma_bf(cc[2 * g2],     eh, bl[0], bl[1]);
                    mma_bf(cc[2 * g2 + 1], eh, bl[2], bl[3]);
                    mma_bf(cc[2 * g2],     el, bh[0], bh[1]);
                    mma_bf(cc[2 * g2 + 1], el, bh[2], bh[3]);
                }
            }
        }

        __syncthreads();
        if (nt < 15) {
            cpa_v64(Vh + (nt + 1) * 128 + 64, sVbH, tid);
            cpa_v64(Vl + (nt + 1) * 128 + 64, sVbL, tid);
            CPC();
        }
    }

    #pragma unroll
    for (int o = 1; o <= 2; o <<= 1) {
        rs0 += __shfl_xor_sync(0xffffffffu, rs0, o);
        rs1 += __shfl_xor_sync(0xffffffffu, rs1, o);
    }
    const float I0 = 1.f / rs0;
    const float I1 = 1.f / rs1;
    if (tq == 0) {
        g_rowI[(size_t)zz * LLS + lq0] = I0;
        g_rowI[(size_t)zz * LLS + lq0 + 8] = I1;
    }

    #pragma unroll
    for (int g = 0; g < 8; g++) {
        int d = g * 8 + 2 * tq;
        #pragma unroll
        for (int rr = 0; rr < 2; rr++) {
            int t = b * LLS + lq0 + rr * 8;
            float In = rr ? I1 : I0;
            uint32_t hv, lv;
            split2(cc[g][rr * 2] * In, cc[g][rr * 2 + 1] * In, hv, lv);
            size_t base = (size_t)t * DDM + h * 64 + d;
            *(uint32_t*)(g_ctx_hi + base) = hv;
            *(uint32_t*)(g_ctx_lo + base) = lv;
        }
    }
}

// ===========================================================================
// Kernel 4: outproj + FUSED P-scale (corrected coverage).
// Each of the 128 CTAs normalizes P rows [cid*256, cid*256+256),
// 32 rows per K-chunk, interleaved with the cp.async pipeline.
// ===========================================================================
__global__ __launch_bounds__(256) void outproj_kernel(
    const float* __restrict__ q, const float* __restrict__ bo, float* __restrict__ attn)
{
    extern __shared__ char sm[];
    const int tid = threadIdx.x, lane = tid & 31, w = tid >> 5;
    const int gid = lane >> 2, tq = lane & 3;
    const int m0 = blockIdx.y * 128, n0 = blockIdx.x * 128;
    const int cid = blockIdx.y * 4 + blockIdx.x;     // 0..127

    const __nv_bfloat16* Ah = g_ctx_hi + (size_t)m0 * DDM;
    const __nv_bfloat16* Al = g_ctx_lo + (size_t)m0 * DDM;
    const __nv_bfloat16* Bh = g_w_hi + (size_t)3 * DDM * DDM + (size_t)n0 * DDM;
    const __nv_bfloat16* Bl = g_w_lo + (size_t)3 * DDM * DDM + (size_t)n0 * DDM;

    uint32_t s0 = cvs(sm);

    cpa_bf64(Ah, DDM, s0, tid);
    cpa_bf64(Al, DDM, s0 + 18432, tid);
    cpa_bf64(Bh, DDM, s0 + 36864, tid);
    cpa_bf64(Bl, DDM, s0 + 55296, tid);
    CPC();

    float c[16][4];
    #pragma unroll
    for (int i = 0; i < 16; i++)
        #pragma unroll
        for (int j = 0; j < 4; j++) c[i][j] = 0.f;

    for (int c8 = 0; c8 < 8; c8++) {
        // ---- fused scale slice: 32 P rows while cp.async group lands ----
        {
            int rbase = cid * 256 + c8 * 32;
            #pragma unroll 2
            for (int r = 0; r < 32; r++) {
                int row = rbase + r;
                float Iv = g_rowI[row];
                float4* p = (float4*)(attn + (size_t)row * LLS);
                float4 a = p[tid];
                float4 bq4 = p[tid + 256];
                a.x *= Iv; a.y *= Iv; a.z *= Iv; a.w *= Iv;
                bq4.x *= Iv; bq4.y *= Iv; bq4.z *= Iv; bq4.w *= Iv;
                p[tid] = a;
                p[tid + 256] = bq4;
            }
        }

        CPW0();
        __syncthreads();
        uint32_t sb = s0 + (c8 & 1) * 73728;
        if (c8 < 7) {
            uint32_t sn = s0 + ((c8 + 1) & 1) * 73728;
            int off = (c8 + 1) * 64;
            cpa_bf64(Ah + off, DDM, sn, tid);
            cpa_bf64(Al + off, DDM, sn + 18432, tid);
            cpa_bf64(Bh + off, DDM, sn + 36864, tid);
            cpa_bf64(Bl + off, DDM, sn + 55296, tid);
            CPC();
        }
        mma_chunk128(c, sb, sb + 18432, sb + 36864, sb + 55296, w * 16, lane);
    }

    #pragma unroll
    for (int g = 0; g < 16; g++) {
        int n = n0 + g * 8 + 2 * tq;
        float b0 = bo[n], b1 = bo[n + 1];
        #pragma unroll
        for (int rr = 0; rr < 2; rr++) {
            int t = m0 + w * 16 + gid + rr * 8;
            const float* res = q + (size_t)t * DDM + n;
            float v0 = c[g][rr * 2] + b0 + res[0];
            float v1 = c[g][rr * 2 + 1] + b1 + res[1];
            *(float2*)(g_tmp + (size_t)t * DDM + n) = make_float2(v0, v1);
        }
    }
}

// ===========================================================================
// Kernel 5: LayerNorm per token -> d_out
// ===========================================================================
__global__ __launch_bounds__(256) void ln_kernel(
    const float* __restrict__ gamma, const float* __restrict__ beta,
    float* __restrict__ out)
{
    const int t = blockIdx.x;
    const float* x = g_tmp + (size_t)t * DDM;
    const int tid = threadIdx.x;
    __shared__ float red1[8], red2[8];

    float a = x[tid], b = x[tid + 256];
    float s = a + b;
    float ss = a * a + b * b;
    #pragma unroll
    for (int o = 16; o; o >>= 1) {
        s  += __shfl_xor_sync(0xffffffffu, s, o);
        ss += __shfl_xor_sync(0xffffffffu, ss, o);
    }
    if ((tid & 31) == 0) { red1[tid >> 5] = s; red2[tid >> 5] = ss; }
    __syncthreads();
    if (tid < 32) {
        float u = (tid < 8) ? red1[tid] : 0.f;
        float wv = (tid < 8) ? red2[tid] : 0.f;
        #pragma unroll
        for (int o = 4; o; o >>= 1) {
            u  += __shfl_xor_sync(0xffffffffu, u, o);
            wv += __shfl_xor_sync(0xffffffffu, wv, o);
        }
        if (tid == 0) { red1[0] = u; red2[0] = wv; }
    }
    __syncthreads();
    const float mu = red1[0] * (1.f / DDM);
    const float var = red2[0] * (1.f / DDM) - mu * mu;
    const float rstd = rsqrtf(var + 1e-5f);

    out[(size_t)t * DDM + tid]       = (a - mu) * rstd * gamma[tid]       + beta[tid];
    out[(size_t)t * DDM + tid + 256] = (b - mu) * rstd * gamma[tid + 256] + beta[tid + 256];
}

// ===========================================================================
extern "C" void kernel_launch(void* const* d_in, const int* in_sizes, int n_in,
                              void* d_out, int out_size)
{
    const float* q     = (const float*)d_in[0];
    const float* k     = (const float*)d_in[1];
    const float* v     = (const float*)d_in[2];
    const unsigned char* mask = (const unsigned char*)d_in[3];
    const float* Wq    = (const float*)d_in[4];
    const float* bq    = (const float*)d_in[5];
    const float* Wk    = (const float*)d_in[6];
    const float* bk    = (const float*)d_in[7];
    const float* Wv    = (const float*)d_in[8];
    const float* bv    = (const float*)d_in[9];
    const float* Wo    = (const float*)d_in[10];
    const float* bo    = (const float*)d_in[11];
    const float* gamma = (const float*)d_in[12];
    const float* beta  = (const float*)d_in[13];

    float* out  = (float*)d_out;
    float* attn = out + OUT_ELEMS;

    static int inited = 0;
    if (!inited) {
        cudaFuncSetAttribute(proj_kernel,    cudaFuncAttributeMaxDynamicSharedMemorySize, 147456);
        cudaFuncSetAttribute(attn_kernel,    cudaFuncAttributeMaxDynamicSharedMemorySize, 73728);
        cudaFuncSetAttribute(outproj_kernel, cudaFuncAttributeMaxDynamicSharedMemorySize, 147456);
        inited = 1;
    }

    split_kernel<<<dim3(256, 7), 256>>>(q, k, v, Wq, Wk, Wv, Wo);
    proj_kernel<<<dim3(4, 32, 3), 256, 147456>>>(bq, bk, bv);
    normM_kernel<<<NZ, 256>>>();
    attn_kernel<<<dim3(16, 16), 256, 73728>>>(mask, attn);
    outproj_kernel<<<dim3(4, 32), 256, 147456>>>(q, bo, attn);
    ln_kernel<<<TOKENS, 256>>>(gamma, beta, out);
}

// round 16
// speedup vs baseline: 1.2652x; 1.2652x over previous
#include <cuda_runtime.h>
#include <cuda_bf16.h>
#include <math.h>
#include <stdint.h>

#define LLS 2048
#define DDM 512
#define NZ  16                 // B*H
#define TOKENS 4096
#define OUT_ELEMS (TOKENS*DDM)
#define SA 72                  // padded K-stride for 64-wide operand tiles
#define NEGINF __int_as_float(0xff800000)

// ------------------------- scratch (no allocs) -----------------------------
__device__ __align__(16) __nv_bfloat16 g_in_hi[3*TOKENS*DDM];   // q,k,v pre-split
__device__ __align__(16) __nv_bfloat16 g_in_lo[3*TOKENS*DDM];
__device__ __align__(16) __nv_bfloat16 g_w_hi[4*DDM*DDM];       // Wq,Wk,Wv,Wo
__device__ __align__(16) __nv_bfloat16 g_w_lo[4*DDM*DDM];
__device__ __align__(16) __nv_bfloat16 g_q_hi[NZ*LLS*64];
__device__ __align__(16) __nv_bfloat16 g_q_lo[NZ*LLS*64];
__device__ __align__(16) __nv_bfloat16 g_k_hi[NZ*LLS*64];
__device__ __align__(16) __nv_bfloat16 g_k_lo[NZ*LLS*64];
__device__ __align__(16) __nv_bfloat16 g_vt_hi[NZ*64*LLS];      // [bz][d][lk]
__device__ __align__(16) __nv_bfloat16 g_vt_lo[NZ*64*LLS];
__device__ __align__(16) __nv_bfloat16 g_ctx_hi[TOKENS*DDM];
__device__ __align__(16) __nv_bfloat16 g_ctx_lo[TOKENS*DDM];
__device__ float g_M[NZ];
__device__ float g_rowI[NZ*LLS];
__device__ float g_tmp[TOKENS*DDM];

// ------------------------------ helpers ------------------------------------
static __device__ __forceinline__ uint32_t cvs(const void* p) {
    uint32_t a;
    asm("{ .reg .u64 t; cvta.to.shared.u64 t, %1; cvt.u32.u64 %0, t; }" : "=r"(a) : "l"(p));
    return a;
}
static __device__ __forceinline__ void ldsm4(uint32_t* r, uint32_t a) {
    asm volatile("ldmatrix.sync.aligned.m8n8.x4.shared.b16 {%0,%1,%2,%3}, [%4];"
        : "=r"(r[0]), "=r"(r[1]), "=r"(r[2]), "=r"(r[3]) : "r"(a));
}
static __device__ __forceinline__ void mma_bf(float* d, const uint32_t* a, uint32_t b0, uint32_t b1) {
    asm volatile("mma.sync.aligned.m16n8k16.row.col.f32.bf16.bf16.f32 "
        "{%0,%1,%2,%3},{%4,%5,%6,%7},{%8,%9},{%0,%1,%2,%3};"
        : "+f"(d[0]), "+f"(d[1]), "+f"(d[2]), "+f"(d[3])
        : "r"(a[0]), "r"(a[1]), "r"(a[2]), "r"(a[3]), "r"(b0), "r"(b1));
}
#define CPC()  asm volatile("cp.async.commit_group;" ::: "memory")
#define CPW0() asm volatile("cp.async.wait_group 0;" ::: "memory")
#define CPW1() asm volatile("cp.async.wait_group 1;" ::: "memory")

static __device__ __forceinline__ void cpa16(uint32_t dst, const void* src) {
    asm volatile("cp.async.cg.shared.global [%0], [%1], 16;" :: "r"(dst), "l"(src));
}
// bf16 [128][64] tile (row stride ld) -> smem [128][SA] via cp.async
static __device__ __forceinline__ void cpa_bf64(const __nv_bfloat16* __restrict__ src, int ld,
                                                uint32_t dst, int tid) {
    #pragma unroll
    for (int i = 0; i < 4; i++) {
        int idx = i * 256 + tid, row = idx >> 3, c = (idx & 7) * 8;
        cpa16(dst + (uint32_t)(row * SA + c) * 2, src + (size_t)row * ld + c);
    }
}
// bf16 [64][64] tile (row stride LLS) -> smem [64][SA] via cp.async
static __device__ __forceinline__ void cpa_v64(const __nv_bfloat16* __restrict__ src,
                                               uint32_t dst, int tid) {
    #pragma unroll
    for (int i = 0; i < 2; i++) {
        int idx = i * 256 + tid, row = idx >> 3, c = (idx & 7) * 8;
        cpa16(dst + (uint32_t)(row * SA + c) * 2, src + (size_t)row * LLS + c);
    }
}
static __device__ __forceinline__ uint32_t pk2(__nv_bfloat16 a, __nv_bfloat16 b) {
    __nv_bfloat162 t = __halves2bfloat162(a, b);
    return *reinterpret_cast<uint32_t*>(&t);
}
static __device__ __forceinline__ void split2(float x, float y, uint32_t& h, uint32_t& l) {
    __nv_bfloat16 hx = __float2bfloat16(x), hy = __float2bfloat16(y);
    h = pk2(hx, hy);
    l = pk2(__float2bfloat16(x - __bfloat162float(hx)),
            __float2bfloat16(y - __bfloat162float(hy)));
}
static __device__ __forceinline__ uint32_t aoff(int row0, int k0, int stride, int lane) {
    return (uint32_t)((row0 + (lane & 15)) * stride + k0 + ((lane >> 4) << 3)) * 2;
}
static __device__ __forceinline__ uint32_t boff(int n0, int k0, int stride, int lane) {
    return (uint32_t)((n0 + ((lane >> 4) << 3) + (lane & 7)) * stride + k0 + (((lane >> 3) & 1) << 3)) * 2;
}

// 3-term split GEMM chunk with B-fragment reuse: c[16][4] += A*B, K=64
static __device__ __forceinline__ void mma_chunk128(float (*c)[4],
        uint32_t sAh, uint32_t sAl, uint32_t sBh, uint32_t sBl, int wrow, int lane) {
    #pragma unroll
    for (int kk = 0; kk < 4; kk++) {
        uint32_t ah[4], al[4];
        ldsm4(ah, sAh + aoff(wrow, kk * 16, SA, lane));
        ldsm4(al, sAl + aoff(wrow, kk * 16, SA, lane));
        #pragma unroll
        for (int g = 0; g < 8; g++) {
            uint32_t bh[4], bl[4];
            ldsm4(bh, sBh + boff(g * 16, kk * 16, SA, lane));
            ldsm4(bl, sBl + boff(g * 16, kk * 16, SA, lane));
            mma_bf(c[2 * g],     ah, bh[0], bh[1]);
            mma_bf(c[2 * g + 1], ah, bh[2], bh[3]);
            mma_bf(c[2 * g],     ah, bl[0], bl[1]);
            mma_bf(c[2 * g + 1], ah, bl[2], bl[3]);
            mma_bf(c[2 * g],     al, bh[0], bh[1]);
            mma_bf(c[2 * g + 1], al, bh[2], bh[3]);
        }
    }
}

// ===========================================================================
// Kernel 0: pre-split fp32 inputs to bf16 hi/lo.
// ===========================================================================
__global__ __launch_bounds__(256) void split_kernel(
    const float* __restrict__ q, const float* __restrict__ k, const float* __restrict__ v,
    const float* __restrict__ Wq, const float* __restrict__ Wk,
    const float* __restrict__ Wv, const float* __restrict__ Wo)
{
    const int z = blockIdx.y;
    const float* src;
    __nv_bfloat16 *hi, *lo;
    int n4;
    if (z < 3) {
        src = (z == 0) ? q : (z == 1) ? k : v;
        hi = g_in_hi + (size_t)z * TOKENS * DDM;
        lo = g_in_lo + (size_t)z * TOKENS * DDM;
        n4 = TOKENS * DDM / 4;
    } else {
        src = (z == 3) ? Wq : (z == 4) ? Wk : (z == 5) ? Wv : Wo;
        hi = g_w_hi + (size_t)(z - 3) * DDM * DDM;
        lo = g_w_lo + (size_t)(z - 3) * DDM * DDM;
        n4 = DDM * DDM / 4;
    }
    for (int i = blockIdx.x * 256 + threadIdx.x; i < n4; i += gridDim.x * 256) {
        float4 f = ((const float4*)src)[i];
        uint32_t h0, l0, h1, l1;
        split2(f.x, f.y, h0, l0);
        split2(f.z, f.w, h1, l1);
        ((uint2*)hi)[i] = make_uint2(h0, h1);
        ((uint2*)lo)[i] = make_uint2(l0, l1);
    }
}

// ===========================================================================
// Kernel 1: projections (pure-bf16, cp.async double-buffered, BK=64).
// ===========================================================================
__global__ __launch_bounds__(256) void proj_kernel(
    const float* __restrict__ bq, const float* __restrict__ bk, const float* __restrict__ bv)
{
    extern __shared__ char sm[];
    const int tid = threadIdx.x, lane = tid & 31, w = tid >> 5;
    const int gid = lane >> 2, tq = lane & 3;
    const int z = blockIdx.z;

    const __nv_bfloat16 *Ah, *Al, *Bh, *Bl;
    const float* bias;
    int m0, n0;
    if (z == 2) {
        m0 = blockIdx.x * 128;   // dim
        n0 = blockIdx.y * 128;   // token
        Ah = g_w_hi + (size_t)2 * DDM * DDM + (size_t)m0 * DDM;
        Al = g_w_lo + (size_t)2 * DDM * DDM + (size_t)m0 * DDM;
        Bh = g_in_hi + (size_t)2 * TOKENS * DDM + (size_t)n0 * DDM;
        Bl = g_in_lo + (size_t)2 * TOKENS * DDM + (size_t)n0 * DDM;
        bias = bv;
    } else {
        m0 = blockIdx.y * 128;   // token
        n0 = blockIdx.x * 128;   // out-dim
        Ah = g_in_hi + (size_t)z * TOKENS * DDM + (size_t)m0 * DDM;
        Al = g_in_lo + (size_t)z * TOKENS * DDM + (size_t)m0 * DDM;
        Bh = g_w_hi + (size_t)z * DDM * DDM + (size_t)n0 * DDM;
        Bl = g_w_lo + (size_t)z * DDM * DDM + (size_t)n0 * DDM;
        bias = (z == 0) ? bq : bk;
    }

    uint32_t s0 = cvs(sm);

    cpa_bf64(Ah, DDM, s0, tid);
    cpa_bf64(Al, DDM, s0 + 18432, tid);
    cpa_bf64(Bh, DDM, s0 + 36864, tid);
    cpa_bf64(Bl, DDM, s0 + 55296, tid);
    CPC();

    float c[16][4];
    #pragma unroll
    for (int i = 0; i < 16; i++)
        #pragma unroll
        for (int j = 0; j < 4; j++) c[i][j] = 0.f;

    for (int c8 = 0; c8 < 8; c8++) {
        CPW0();
        __syncthreads();
        uint32_t sb = s0 + (c8 & 1) * 73728;
        if (c8 < 7) {
            uint32_t sn = s0 + ((c8 + 1) & 1) * 73728;
            int off = (c8 + 1) * 64;
            cpa_bf64(Ah + off, DDM, sn, tid);
            cpa_bf64(Al + off, DDM, sn + 18432, tid);
            cpa_bf64(Bh + off, DDM, sn + 36864, tid);
            cpa_bf64(Bl + off, DDM, sn + 55296, tid);
            CPC();
        }
        mma_chunk128(c, sb, sb + 18432, sb + 36864, sb + 55296, w * 16, lane);
    }

    if (z < 2) {
        __nv_bfloat16* Ohi = (z == 0) ? g_q_hi : g_k_hi;
        __nv_bfloat16* Olo = (z == 0) ? g_q_lo : g_k_lo;
        #pragma unroll
        for (int g = 0; g < 16; g++) {
            int n = n0 + g * 8 + 2 * tq;
            float b0 = bias[n], b1 = bias[n + 1];
            int head = n >> 6, d = n & 63;
            #pragma unroll
            for (int rr = 0; rr < 2; rr++) {
                int t = m0 + w * 16 + gid + rr * 8;
                int bb = t >> 11, l = t & 2047;
                float v0 = c[g][rr * 2] + b0, v1 = c[g][rr * 2 + 1] + b1;
                uint32_t h, lo;
                split2(v0, v1, h, lo);
                size_t base = (((size_t)(bb * 8 + head)) * LLS + l) * 64 + d;
                *(uint32_t*)(Ohi + base) = h;
                *(uint32_t*)(Olo + base) = lo;
            }
        }
    } else {
        #pragma unroll
        for (int g = 0; g < 16; g++) {
            int n = n0 + g * 8 + 2 * tq;     // token
            int bb = n >> 11, l = n & 2047;
            #pragma unroll
            for (int rr = 0; rr < 2; rr++) {
                int m = m0 + w * 16 + gid + rr * 8;   // dim
                int head = m >> 6, d = m & 63;
                float bm = bias[m];
                float v0 = c[g][rr * 2] + bm, v1 = c[g][rr * 2 + 1] + bm;
                uint32_t h, lo;
                split2(v0, v1, h, lo);
                size_t base = (((size_t)(bb * 8 + head)) * 64 + d) * LLS + l;
                *(uint32_t*)(g_vt_hi + base) = h;
                *(uint32_t*)(g_vt_lo + base) = lo;
            }
        }
    }
}

// ===========================================================================
// Kernel 2: per-(b,h) softmax shift M = 0.5*sqrt(mean||q||^2)*sqrt(mean||k||^2)
// ===========================================================================
static __device__ __forceinline__ float ssqw(uint32_t w) {
    float2 f = __bfloat1622float2(*reinterpret_cast<__nv_bfloat162*>(&w));
    return f.x * f.x + f.y * f.y;
}
__global__ __launch_bounds__(256) void normM_kernel()
{
    const int bz = blockIdx.x, tid = threadIdx.x;
    const uint4* qp = (const uint4*)(g_q_hi + (size_t)bz * LLS * 64);
    const uint4* kp = (const uint4*)(g_k_hi + (size_t)bz * LLS * 64);
    float sq = 0.f, sk = 0.f;
    for (int i = tid; i < LLS * 64 / 8; i += 256) {
        uint4 a = qp[i];
        sq += ssqw(a.x) + ssqw(a.y) + ssqw(a.z) + ssqw(a.w);
        uint4 b = kp[i];
        sk += ssqw(b.x) + ssqw(b.y) + ssqw(b.z) + ssqw(b.w);
    }
    __shared__ float r1[8], r2[8];
    #pragma unroll
    for (int o = 16; o; o >>= 1) {
        sq += __shfl_xor_sync(0xffffffffu, sq, o);
        sk += __shfl_xor_sync(0xffffffffu, sk, o);
    }
    if ((tid & 31) == 0) { r1[tid >> 5] = sq; r2[tid >> 5] = sk; }
    __syncthreads();
    if (tid == 0) {
        float a = 0.f, b = 0.f;
        #pragma unroll
        for (int j = 0; j < 8; j++) { a += r1[j]; b += r2[j]; }
        g_M[bz] = 0.5f * sqrtf(a / LLS) * sqrtf(b / LLS);
    }
}

// ===========================================================================
// Kernel 3: single-sweep attention with K DOUBLE-BUFFERED smem pipeline.
// smem 110592/CTA, 2 CTAs/SM.  Per tile: ONE cp.async wait + TWO syncs;
// K[nt+2] and V[nt+1] issued at end of nt (full-tile cover).
// ===========================================================================
__global__ __launch_bounds__(256, 2) void attn_kernel(
    const unsigned char* __restrict__ mask, float* __restrict__ attn)
{
    extern __shared__ char sm[];
    const int tid = threadIdx.x, lane = tid & 31, w = tid >> 5;
    const int gid = lane >> 2, tq = lane & 3;
    const int m0 = blockIdx.x * 128, zz = blockIdx.y;
    const int h = zz >> 1, b = zz & 1, bz = b * 8 + h;

    uint32_t s0 = cvs(sm);
    // K buffers: buf0 @0 (hi), @18432 (lo); buf1 @36864 (hi), @55296 (lo)
    // V: VaH @73728, VaL @82944, VbH @92160, VbL @101376
    const uint32_t sVaH = s0 + 73728, sVaL = s0 + 82944;
    const uint32_t sVbH = s0 + 92160, sVbL = s0 + 101376;

    const __nv_bfloat16* Kh = g_k_hi + (size_t)bz * LLS * 64;
    const __nv_bfloat16* Kl = g_k_lo + (size_t)bz * LLS * 64;
    const __nv_bfloat16* Vh = g_vt_hi + (size_t)bz * 64 * LLS;
    const __nv_bfloat16* Vl = g_vt_lo + (size_t)bz * 64 * LLS;
    const float M = g_M[bz];

    // prologue: stage Q in the V area, extract register fragments
    cpa_bf64(g_q_hi + ((size_t)bz * LLS + m0) * 64, 64, sVaH, tid);   // spans Va hi+lo
    cpa_bf64(g_q_lo + ((size_t)bz * LLS + m0) * 64, 64, sVbH, tid);   // spans Vb hi+lo
    CPC();
    CPW0();
    __syncthreads();

    uint32_t qh[4][4], ql[4][4];
    #pragma unroll
    for (int kk = 0; kk < 4; kk++) {
        ldsm4(qh[kk], sVaH + aoff(w * 16, kk * 16, SA, lane));
        ldsm4(ql[kk], sVbH + aoff(w * 16, kk * 16, SA, lane));
    }
    __syncthreads();

    // initial groups: K0 | V0 | K1  (FIFO order matters for CPW1)
    cpa_bf64(Kh, 64, s0, tid);
    cpa_bf64(Kl, 64, s0 + 18432, tid);
    CPC();
    cpa_v64(Vh, sVaH, tid);
    cpa_v64(Vl, sVaL, tid);
    cpa_v64(Vh + 64, sVbH, tid);
    cpa_v64(Vl + 64, sVbL, tid);
    CPC();
    cpa_bf64(Kh + (size_t)128 * 64, 64, s0 + 36864, tid);
    cpa_bf64(Kl + (size_t)128 * 64, 64, s0 + 55296, tid);
    CPC();

    const int lq0 = m0 + w * 16 + gid;
    float rs0 = 0.f, rs1 = 0.f;

    float cc[8][4];
    #pragma unroll
    for (int i = 0; i < 8; i++)
        #pragma unroll
        for (int j = 0; j < 4; j++) cc[i][j] = 0.f;

    for (int nt = 0; nt < 16; nt++) {
        if (nt == 15) CPW0(); else CPW1();   // K[nt] + V[nt] ready
        __syncthreads();

        const uint32_t sKh = s0 + (nt & 1) * 36864;
        const uint32_t sKl = sKh + 18432;

        const unsigned char* mrow = mask + ((size_t)b * LLS + lq0) * LLS + nt * 128;
        float* prow = attn + ((size_t)zz * LLS + lq0) * LLS + nt * 128;

        #pragma unroll
        for (int half = 0; half < 2; half++) {
            float c[8][4];
            #pragma unroll
            for (int i = 0; i < 8; i++)
                #pragma unroll
                for (int j = 0; j < 4; j++) c[i][j] = 0.f;
            #pragma unroll
            for (int kk = 0; kk < 4; kk++) {
                #pragma unroll
                for (int g = 0; g < 4; g++) {
                    uint32_t bh[4], bl[4];
                    uint32_t off = boff((half * 4 + g) * 16, kk * 16, SA, lane);
                    ldsm4(bh, sKh + off);
                    ldsm4(bl, sKl + off);
                    mma_bf(c[2 * g],     qh[kk], bh[0], bh[1]);
                    mma_bf(c[2 * g + 1], qh[kk], bh[2], bh[3]);
                    mma_bf(c[2 * g],     qh[kk], bl[0], bl[1]);
                    mma_bf(c[2 * g + 1], qh[kk], bl[2], bl[3]);
                    mma_bf(c[2 * g],     ql[kk], bh[0], bh[1]);
                    mma_bf(c[2 * g + 1], ql[kk], bh[2], bh[3]);
                }
            }

            const unsigned char* mr0 = mrow + half * 64;
            const unsigned char* mr1 = mr0 + (size_t)8 * LLS;
            float* pr0 = prow + half * 64;
            float* pr1 = pr0 + (size_t)8 * LLS;
            #pragma unroll
            for (int g = 0; g < 8; g++) {
                int nn = g * 8 + 2 * tq;
                unsigned short mw0 = *(const unsigned short*)(mr0 + nn);
                unsigned short mw1 = *(const unsigned short*)(mr1 + nn);
                c[g][0] = (mw0 & 0xFF) ? 0.f : __expf(c[g][0] - M);
                c[g][1] = (mw0 >> 8)   ? 0.f : __expf(c[g][1] - M);
                c[g][2] = (mw1 & 0xFF) ? 0.f : __expf(c[g][2] - M);
                c[g][3] = (mw1 >> 8)   ? 0.f : __expf(c[g][3] - M);
                rs0 += c[g][0] + c[g][1];
                rs1 += c[g][2] + c[g][3];
                *(float2*)(pr0 + nn) = make_float2(c[g][0], c[g][1]);
                *(float2*)(pr1 + nn) = make_float2(c[g][2], c[g][3]);
            }

            uint32_t svh = half ? sVbH : sVaH;
            uint32_t svl = half ? sVbL : sVaL;
            #pragma unroll
            for (int kk2 = 0; kk2 < 4; kk2++) {
                uint32_t eh[4], el[4];
                split2(c[2 * kk2][0],     c[2 * kk2][1],     eh[0], el[0]);
                split2(c[2 * kk2][2],     c[2 * kk2][3],     eh[1], el[1]);
                split2(c[2 * kk2 + 1][0], c[2 * kk2 + 1][1], eh[2], el[2]);
                split2(c[2 * kk2 + 1][2], c[2 * kk2 + 1][3], eh[3], el[3]);
                #pragma unroll
                for (int g2 = 0; g2 < 4; g2++) {
                    uint32_t off = boff(g2 * 16, kk2 * 16, SA, lane);
                    uint32_t bh[4], bl[4];
                    ldsm4(bh, svh + off);
                    ldsm4(bl, svl + off);
                    mma_bf(cc[2 * g2],     eh, bh[0], bh[1]);
                    mma_bf(cc[2 * g2 + 1], eh, bh[2], bh[3]);
                    mma_bf(cc[2 * g2],     eh, bl[0], bl[1]);
                    mma_bf(cc[2 * g2 + 1], eh, bl[2], bl[3]);
                    mma_bf(cc[2 * g2],     el, bh[0], bh[1]);
                    mma_bf(cc[2 * g2 + 1], el, bh[2], bh[3]);
                }
            }
        }

        __syncthreads();   // all warps done with V[nt] and K buf (nt&1)
        if (nt < 15) {
            cpa_v64(Vh + (nt + 1) * 128, sVaH, tid);
            cpa_v64(Vl + (nt + 1) * 128, sVaL, tid);
            cpa_v64(Vh + (nt + 1) * 128 + 64, sVbH, tid);
            cpa_v64(Vl + (nt + 1) * 128 + 64, sVbL, tid);
            CPC();
            if (nt < 14) {
                uint32_t nk = s0 + (nt & 1) * 36864;   // buffer just freed
                cpa_bf64(Kh + (size_t)(nt + 2) * 128 * 64, 64, nk, tid);
                cpa_bf64(Kl + (size_t)(nt + 2) * 128 * 64, 64, nk + 18432, tid);
                CPC();
            }
        }
    }

    #pragma unroll
    for (int o = 1; o <= 2; o <<= 1) {
        rs0 += __shfl_xor_sync(0xffffffffu, rs0, o);
        rs1 += __shfl_xor_sync(0xffffffffu, rs1, o);
    }
    const float I0 = 1.f / rs0;
    const float I1 = 1.f / rs1;
    if (tq == 0) {
        g_rowI[(size_t)zz * LLS + lq0] = I0;
        g_rowI[(size_t)zz * LLS + lq0 + 8] = I1;
    }

    #pragma unroll
    for (int g = 0; g < 8; g++) {
        int d = g * 8 + 2 * tq;
        #pragma unroll
        for (int rr = 0; rr < 2; rr++) {
            int t = b * LLS + lq0 + rr * 8;
            float In = rr ? I1 : I0;
            uint32_t hv, lv;
            split2(cc[g][rr * 2] * In, cc[g][rr * 2 + 1] * In, hv, lv);
            size_t base = (size_t)t * DDM + h * 64 + d;
            *(uint32_t*)(g_ctx_hi + base) = hv;
            *(uint32_t*)(g_ctx_lo + base) = lv;
        }
    }
}

// ===========================================================================
// Kernel 4: scale P rows by 1/rowsum (streaming).
// ===========================================================================
__global__ __launch_bounds__(256) void scale_kernel(float* __restrict__ attn)
{
    const int row = blockIdx.x;
    const float I = g_rowI[row];
    float4* p = (float4*)(attn + (size_t)row * LLS);
    float4 a = p[threadIdx.x];
    float4 b = p[threadIdx.x + 256];
    a.x *= I; a.y *= I; a.z *= I; a.w *= I;
    b.x *= I; b.y *= I; b.z *= I; b.w *= I;
    p[threadIdx.x] = a;
    p[threadIdx.x + 256] = b;
}

// ===========================================================================
// Kernel 5: out = ctx @ Wo^T + bo + residual(q) -> g_tmp  (BK=64 dbl-buffer)
// ===========================================================================
__global__ __launch_bounds__(256) void outproj_kernel(
    const float* __restrict__ q, const float* __restrict__ bo)
{
    extern __shared__ char sm[];
    const int tid = threadIdx.x, lane = tid & 31, w = tid >> 5;
    const int gid = lane >> 2, tq = lane & 3;
    const int m0 = blockIdx.y * 128, n0 = blockIdx.x * 128;

    const __nv_bfloat16* Ah = g_ctx_hi + (size_t)m0 * DDM;
    const __nv_bfloat16* Al = g_ctx_lo + (size_t)m0 * DDM;
    const __nv_bfloat16* Bh = g_w_hi + (size_t)3 * DDM * DDM + (size_t)n0 * DDM;
    const __nv_bfloat16* Bl = g_w_lo + (size_t)3 * DDM * DDM + (size_t)n0 * DDM;

    uint32_t s0 = cvs(sm);

    cpa_bf64(Ah, DDM, s0, tid);
    cpa_bf64(Al, DDM, s0 + 18432, tid);
    cpa_bf64(Bh, DDM, s0 + 36864, tid);
    cpa_bf64(Bl, DDM, s0 + 55296, tid);
    CPC();

    float c[16][4];
    #pragma unroll
    for (int i = 0; i < 16; i++)
        #pragma unroll
        for (int j = 0; j < 4; j++) c[i][j] = 0.f;

    for (int c8 = 0; c8 < 8; c8++) {
        CPW0();
        __syncthreads();
        uint32_t sb = s0 + (c8 & 1) * 73728;
        if (c8 < 7) {
            uint32_t sn = s0 + ((c8 + 1) & 1) * 73728;
            int off = (c8 + 1) * 64;
            cpa_bf64(Ah + off, DDM, sn, tid);
            cpa_bf64(Al + off, DDM, sn + 18432, tid);
            cpa_bf64(Bh + off, DDM, sn + 36864, tid);
            cpa_bf64(Bl + off, DDM, sn + 55296, tid);
            CPC();
        }
        mma_chunk128(c, sb, sb + 18432, sb + 36864, sb + 55296, w * 16, lane);
    }

    #pragma unroll
    for (int g = 0; g < 16; g++) {
        int n = n0 + g * 8 + 2 * tq;
        float b0 = bo[n], b1 = bo[n + 1];
        #pragma unroll
        for (int rr = 0; rr < 2; rr++) {
            int t = m0 + w * 16 + gid + rr * 8;
            const float* res = q + (size_t)t * DDM + n;
            float v0 = c[g][rr * 2] + b0 + res[0];
            float v1 = c[g][rr * 2 + 1] + b1 + res[1];
            *(float2*)(g_tmp + (size_t)t * DDM + n) = make_float2(v0, v1);
        }
    }
}

// ===========================================================================
// Kernel 6: LayerNorm per token -> d_out
// ===========================================================================
__global__ __launch_bounds__(256) void ln_kernel(
    const float* __restrict__ gamma, const float* __restrict__ beta,
    float* __restrict__ out)
{
    const int t = blockIdx.x;
    const float* x = g_tmp + (size_t)t * DDM;
    const int tid = threadIdx.x;
    __shared__ float red1[8], red2[8];

    float a = x[tid], b = x[tid + 256];
    float s = a + b;
    float ss = a * a + b * b;
    #pragma unroll
    for (int o = 16; o; o >>= 1) {
        s  += __shfl_xor_sync(0xffffffffu, s, o);
        ss += __shfl_xor_sync(0xffffffffu, ss, o);
    }
    if ((tid & 31) == 0) { red1[tid >> 5] = s; red2[tid >> 5] = ss; }
    __syncthreads();
    if (tid < 32) {
        float u = (tid < 8) ? red1[tid] : 0.f;
        float wv = (tid < 8) ? red2[tid] : 0.f;
        #pragma unroll
        for (int o = 4; o; o >>= 1) {
            u  += __shfl_xor_sync(0xffffffffu, u, o);
            wv += __shfl_xor_sync(0xffffffffu, wv, o);
        }
        if (tid == 0) { red1[0] = u; red2[0] = wv; }
    }
    __syncthreads();
    const float mu = red1[0] * (1.f / DDM);
    const float var = red2[0] * (1.f / DDM) - mu * mu;
    const float rstd = rsqrtf(var + 1e-5f);

    out[(size_t)t * DDM + tid]       = (a - mu) * rstd * gamma[tid]       + beta[tid];
    out[(size_t)t * DDM + tid + 256] = (b - mu) * rstd * gamma[tid + 256] + beta[tid + 256];
}

// ===========================================================================
extern "C" void kernel_launch(void* const* d_in, const int* in_sizes, int n_in,
                              void* d_out, int out_size)
{
    const float* q     = (const float*)d_in[0];
    const float* k     = (const float*)d_in[1];
    const float* v     = (const float*)d_in[2];
    const unsigned char* mask = (const unsigned char*)d_in[3];
    const float* Wq    = (const float*)d_in[4];
    const float* bq    = (const float*)d_in[5];
    const float* Wk    = (const float*)d_in[6];
    const float* bk    = (const float*)d_in[7];
    const float* Wv    = (const float*)d_in[8];
    const float* bv    = (const float*)d_in[9];
    const float* Wo    = (const float*)d_in[10];
    const float* bo    = (const float*)d_in[11];
    const float* gamma = (const float*)d_in[12];
    const float* beta  = (const float*)d_in[13];

    float* out  = (float*)d_out;
    float* attn = out + OUT_ELEMS;

    static int inited = 0;
    if (!inited) {
        cudaFuncSetAttribute(proj_kernel,    cudaFuncAttributeMaxDynamicSharedMemorySize, 147456);
        cudaFuncSetAttribute(attn_kernel,    cudaFuncAttributeMaxDynamicSharedMemorySize, 110592);
        cudaFuncSetAttribute(outproj_kernel, cudaFuncAttributeMaxDynamicSharedMemorySize, 147456);
        inited = 1;
    }

    split_kernel<<<dim3(256, 7), 256>>>(q, k, v, Wq, Wk, Wv, Wo);
    proj_kernel<<<dim3(4, 32, 3), 256, 147456>>>(bq, bk, bv);
    normM_kernel<<<NZ, 256>>>();
    attn_kernel<<<dim3(16, 16), 256, 110592>>>(mask, attn);
    scale_kernel<<<NZ * LLS, 256>>>(attn);
    outproj_kernel<<<dim3(4, 32), 256, 147456>>>(q, bo);
    ln_kernel<<<TOKENS, 256>>>(gamma, beta, out);
}